// round 3
// baseline (speedup 1.0000x reference)
#include <cuda_runtime.h>
#include <cuda_bf16.h>
#include <math.h>

#define G_    256
#define NMAX  1024
#define EMAX  4096
#define CH    64
#define DDI   128
#define EFD   16
#define NEDDI 4096
#define NT    512
#define NWARP 16

typedef unsigned long long ull;

__device__ float g_h   [(size_t)G_ * NMAX * CH];
__device__ float g_gcn [(size_t)G_ * NMAX * CH];
__device__ float g_pool[(size_t)G_ * NMAX * CH];
__device__ short g_es  [(size_t)G_ * EMAX];
__device__ short g_et  [(size_t)G_ * EMAX];
__device__ float g_ew  [(size_t)G_ * EMAX];
__device__ int   g_ecnt[G_];
__device__ float g_feat[G_ * 2 * CH];
__device__ float g_T   [(size_t)G_ * EFD * DDI];
__device__ float g_tb  [G_ * DDI];
__device__ float g_h2  [G_ * DDI];
__device__ float g_A   [G_ * DDI];
__device__ float g_B   [G_ * DDI];
__device__ float g_lsum[2];

__device__ __forceinline__ ull fma2(ull a, ull b, ull c) {
    ull d; asm("fma.rn.f32x2 %0, %1, %2, %3;" : "=l"(d) : "l"(a), "l"(b), "l"(c)); return d;
}
__device__ __forceinline__ ull pk2(float a) {
    ull r; asm("mov.b64 %0, {%1, %2};" : "=l"(r) : "f"(a), "f"(a)); return r;
}
__device__ __forceinline__ unsigned keyflip(float f) {
    unsigned u = __float_as_uint(f);
    return (u & 0x80000000u) ? ~u : (u | 0x80000000u);
}
__device__ __forceinline__ float sp_f(float x) {
    return fmaxf(x, 0.f) + log1pf(expf(-fabsf(x)));
}

__global__ void k_init(const int* __restrict__ ei, const float* __restrict__ ew) {
    size_t stride = (size_t)gridDim.x * blockDim.x;
    size_t t0 = (size_t)blockIdx.x * blockDim.x + threadIdx.x;
    for (size_t i = t0; i < (size_t)G_ * EMAX; i += stride) {
        size_t g = i >> 12, e = i & 4095;
        const int* base = ei + g * 2 * EMAX;
        g_es[i] = (short)base[e];
        g_et[i] = (short)base[EMAX + e];
        g_ew[i] = ew[i];
    }
    for (size_t i = t0; i < (size_t)G_ * 2 * CH; i += stride) g_feat[i] = 0.f;
    if (t0 < G_) g_ecnt[t0] = EMAX;
    if (t0 < 2)  g_lsum[t0] = 0.f;
}

__global__ void __launch_bounds__(128) k_gemm(const float* __restrict__ xin,
                                              const float* __restrict__ W) {
    __shared__ __align__(16) float sW[CH * CH];
    int tid = threadIdx.x;
    for (int i = tid; i < CH * CH; i += 128) sW[i] = W[i];
    __syncthreads();
    int g = blockIdx.y;
    int r = blockIdx.x * 128 + tid;
    const float4* xr = reinterpret_cast<const float4*>(xin + ((size_t)g * NMAX + r) * CH);
    const ull* W2 = reinterpret_cast<const ull*>(sW);
    ull acc[32];
#pragma unroll
    for (int o = 0; o < 32; o++) acc[o] = 0ull;
#pragma unroll 1
    for (int kk = 0; kk < 16; kk++) {
        float4 xv = xr[kk];
        const ull* wr = W2 + kk * 4 * 32;
        ull x0 = pk2(xv.x), x1 = pk2(xv.y), x2 = pk2(xv.z), x3 = pk2(xv.w);
#pragma unroll
        for (int o = 0; o < 32; o++) acc[o] = fma2(x0, wr[o], acc[o]);
#pragma unroll
        for (int o = 0; o < 32; o++) acc[o] = fma2(x1, wr[32 + o], acc[o]);
#pragma unroll
        for (int o = 0; o < 32; o++) acc[o] = fma2(x2, wr[64 + o], acc[o]);
#pragma unroll
        for (int o = 0; o < 32; o++) acc[o] = fma2(x3, wr[96 + o], acc[o]);
    }
    ull* orow = reinterpret_cast<ull*>(g_h + ((size_t)g * NMAX + r) * CH);
#pragma unroll
    for (int o = 0; o < 32; o++) orow[o] = acc[o];
}

struct SG {
    ull   keys[NMAX];
    short es[EMAX]; short et[EMAX]; float ew[EMAX]; short eord[EMAX];
    int   rowptr[NMAX + 1]; int cnt[NMAX];
    float dinv[NMAX]; float pdot[NMAX]; float score[NMAX];
    short newid[NMAX];
    float wroot[CH], wnbr[CH], bias[CH];
    float pmax[NWARP][CH]; float psum[NWARP][CH];
    int   scan[NWARP + 1];
    float sbv; int base;
};

__device__ int blockScanExcl(int v, int* sscan, int tid, int* totalOut) {
    __syncthreads();
    int lane = tid & 31, w = tid >> 5, x = v;
#pragma unroll
    for (int o = 1; o < 32; o <<= 1) {
        int y = __shfl_up_sync(0xFFFFFFFFu, x, o);
        if (lane >= o) x += y;
    }
    if (lane == 31) sscan[w] = x;
    __syncthreads();
    if (w == 0) {
        int t = (lane < NWARP) ? sscan[lane] : 0;
#pragma unroll
        for (int o = 1; o < NWARP; o <<= 1) {
            int y = __shfl_up_sync(0xFFFFFFFFu, t, o);
            if (lane >= o) t += y;
        }
        if (lane < NWARP) sscan[lane] = t;
    }
    __syncthreads();
    int wOff = w ? sscan[w - 1] : 0;
    *totalOut = sscan[NWARP - 1];
    return wOff + (x - v);
}

template <int N, int K>
__global__ void __launch_bounds__(NT) k_graph(const float* __restrict__ sroot,
                                              const float* __restrict__ snbr,
                                              const float* __restrict__ sbp,
                                              const float* __restrict__ bvec) {
    extern __shared__ char smraw[];
    SG& S = *reinterpret_cast<SG*>(smraw);
    int tid = threadIdx.x, lane = tid & 31, w = tid >> 5;
    int g = blockIdx.x;
    int E = g_ecnt[g];
    size_t gbase = (size_t)g * NMAX * CH;
    size_t ebase = (size_t)g * EMAX;

    for (int e = tid; e < E; e += NT) {
        S.es[e] = g_es[ebase + e]; S.et[e] = g_et[ebase + e]; S.ew[e] = g_ew[ebase + e];
    }
    for (int i = tid; i < N; i += NT) { S.dinv[i] = 1.0f; S.cnt[i] = 0; }
    if (tid < CH) { S.wroot[tid] = sroot[tid]; S.wnbr[tid] = snbr[tid]; S.bias[tid] = bvec[tid]; }
    if (tid == 0) S.sbv = sbp[0];
    __syncthreads();

    for (int e = tid; e < E; e += NT) {
        int t = S.et[e];
        atomicAdd(&S.dinv[t], S.ew[e]);
        atomicAdd(&S.cnt[t], 1);
    }
    __syncthreads();
    for (int i = tid; i < N; i += NT) S.dinv[i] = rsqrtf(S.dinv[i]);

    const int EPT = (N + NT - 1) / NT;
    int b0 = tid * EPT, mysum = 0;
#pragma unroll
    for (int q = 0; q < EPT; q++) { int i = b0 + q; if (i < N) mysum += S.cnt[i]; }
    int tot;
    int off = blockScanExcl(mysum, S.scan, tid, &tot);
#pragma unroll
    for (int q = 0; q < EPT; q++) {
        int i = b0 + q;
        if (i < N) { S.rowptr[i] = off; off += S.cnt[i]; }
    }
    if (tid == 0) S.rowptr[N] = E;
    __syncthreads();
    for (int i = tid; i < N; i += NT) S.cnt[i] = 0;
    __syncthreads();
    for (int e = tid; e < E; e += NT) {
        int t = S.et[e];
        S.eord[S.rowptr[t] + atomicAdd(&S.cnt[t], 1)] = (short)e;
    }
    __syncthreads();

    const int c0 = lane, c1 = lane + 32;
    for (int t = w; t < N; t += NWARP) {
        const float* hr = g_h + gbase + (size_t)t * CH;
        float dt = S.dinv[t];
        float a0 = dt * dt * hr[c0], a1 = dt * dt * hr[c1];
        int rb = S.rowptr[t], re = S.rowptr[t + 1];
#pragma unroll 2
        for (int ii = rb; ii < re; ii++) {
            int e = S.eord[ii];
            int s = S.es[e];
            float cf = S.dinv[s] * S.ew[e] * dt;
            const float* hs = g_h + gbase + (size_t)s * CH;
            a0 += cf * hs[c0];
            a1 += cf * hs[c1];
        }
        float v0 = fmaxf(a0 + S.bias[c0], 0.f), v1 = fmaxf(a1 + S.bias[c1], 0.f);
        float* gr = g_gcn + gbase + (size_t)t * CH;
        gr[c0] = v0; gr[c1] = v1;
        float pv = v0 * S.wnbr[c0] + v1 * S.wnbr[c1];
        float qv = v0 * S.wroot[c0] + v1 * S.wroot[c1];
#pragma unroll
        for (int o = 16; o > 0; o >>= 1) {
            pv += __shfl_xor_sync(0xFFFFFFFFu, pv, o);
            qv += __shfl_xor_sync(0xFFFFFFFFu, qv, o);
        }
        if (lane == 0) { S.pdot[t] = pv; S.score[t] = qv + S.sbv; }
    }
    __syncthreads();

    for (int t = tid; t < N; t += NT) {
        float acc = 0.f;
        for (int ii = S.rowptr[t]; ii < S.rowptr[t + 1]; ii++) {
            int e = S.eord[ii];
            acc += S.ew[e] * S.pdot[S.es[e]];
        }
        S.score[t] += acc;
    }
    __syncthreads();

    for (int i = tid; i < N; i += NT)
        S.keys[i] = ((ull)keyflip(S.score[i]) << 32) | (ull)(0xFFFFFFFFu - (unsigned)i);
    for (int k2 = 2; k2 <= N; k2 <<= 1)
        for (int j = k2 >> 1; j > 0; j >>= 1) {
            __syncthreads();
            for (int i = tid; i < N; i += NT) {
                int ij = i ^ j;
                if (ij > i) {
                    ull a = S.keys[i], b = S.keys[ij];
                    bool dsc = ((i & k2) == 0);
                    if (dsc ? (a < b) : (a > b)) { S.keys[i] = b; S.keys[ij] = a; }
                }
            }
        }
    __syncthreads();

    S.pmax[w][c0] = -3.4e38f; S.pmax[w][c1] = -3.4e38f;
    S.psum[w][c0] = 0.f;      S.psum[w][c1] = 0.f;
    for (int j = w; j < K; j += NWARP) {
        unsigned idx = 0xFFFFFFFFu - (unsigned)(S.keys[j] & 0xFFFFFFFFull);
        float tv = tanhf(S.score[idx]);
        const float* gr = g_gcn + gbase + (size_t)idx * CH;
        float u0 = gr[c0] * tv, u1 = gr[c1] * tv;
        float* pr = g_pool + gbase + (size_t)j * CH;
        pr[c0] = u0; pr[c1] = u1;
        S.pmax[w][c0] = fmaxf(S.pmax[w][c0], u0);
        S.pmax[w][c1] = fmaxf(S.pmax[w][c1], u1);
        S.psum[w][c0] += u0; S.psum[w][c1] += u1;
    }
    __syncthreads();
    if (tid < CH) {
        float mx = -3.4e38f, sm = 0.f;
#pragma unroll
        for (int ww = 0; ww < NWARP; ww++) {
            mx = fmaxf(mx, S.pmax[ww][tid]);
            sm += S.psum[ww][tid];
        }
        g_feat[g * 2 * CH + tid]      += mx;
        g_feat[g * 2 * CH + CH + tid] += sm * (1.0f / K);
    }

    for (int i = tid; i < N; i += NT) S.newid[i] = -1;
    __syncthreads();
    for (int j = tid; j < K; j += NT) {
        unsigned idx = 0xFFFFFFFFu - (unsigned)(S.keys[j] & 0xFFFFFFFFull);
        S.newid[idx] = (short)j;
    }
    if (tid == 0) S.base = 0;
    __syncthreads();
    for (int c = 0; c < E; c += NT) {
        int e = c + tid;
        short sv = 0, tv2 = 0; float wv = 0.f; bool keep = false;
        if (e < E) {
            sv = S.newid[S.es[e]]; tv2 = S.newid[S.et[e]]; wv = S.ew[e];
            keep = (sv >= 0) && (tv2 >= 0);
        }
        int myb = S.base, tot2;
        int pos = blockScanExcl(keep ? 1 : 0, S.scan, tid, &tot2);
        if (keep) { S.es[myb + pos] = sv; S.et[myb + pos] = tv2; S.ew[myb + pos] = wv; }
        __syncthreads();
        if (tid == 0) S.base = myb + tot2;
        __syncthreads();
    }
    int E2 = S.base;
    for (int e = tid; e < E2; e += NT) {
        g_es[ebase + e] = S.es[e]; g_et[ebase + e] = S.et[e]; g_ew[ebase + e] = S.ew[e];
    }
    if (tid == 0) g_ecnt[g] = E2;
}

__global__ void __launch_bounds__(DDI) k_T(const float* __restrict__ Wnn,
                                           const float* __restrict__ bnn) {
    __shared__ float sf[2 * CH];
    int g = blockIdx.x, o = threadIdx.x;
    if (o < 2 * CH) sf[o] = g_feat[g * 2 * CH + o];
    __syncthreads();
    float acc[EFD + 1];
#pragma unroll
    for (int f = 0; f <= EFD; f++) acc[f] = 0.f;
    for (int i = 0; i < 2 * CH; i++) {
        float fv = sf[i];
#pragma unroll
        for (int f = 0; f < EFD; f++)
            acc[f] += fv * Wnn[(size_t)f * 16384 + i * DDI + o];
        acc[EFD] += fv * bnn[i * DDI + o];
    }
#pragma unroll
    for (int f = 0; f < EFD; f++) g_T[((size_t)g * EFD + f) * DDI + o] = acc[f];
    g_tb[g * DDI + o] = acc[EFD];
}

__global__ void __launch_bounds__(DDI) k_hinit(const float* __restrict__ Wroot,
                                               const float* __restrict__ bc4) {
    __shared__ float sf[2 * CH];
    int g = blockIdx.x, o = threadIdx.x;
    if (o < 2 * CH) sf[o] = g_feat[g * 2 * CH + o];
    __syncthreads();
    float acc = bc4[o];
    for (int i = 0; i < 2 * CH; i++) acc += sf[i] * Wroot[i * DDI + o];
    g_h2[g * DDI + o] = acc;
}

__global__ void __launch_bounds__(DDI) k_msg(const float* __restrict__ attr,
                                             const int* __restrict__ dei) {
    int e = blockIdx.x, o = threadIdx.x;
    int s = dei[e], t = dei[NEDDI + e];
    __shared__ float sa[EFD];
    if (o < EFD) sa[o] = attr[e * EFD + o];
    __syncthreads();
    const float* Tp = g_T + (size_t)s * EFD * DDI + o;
    float m = g_tb[s * DDI + o];
#pragma unroll
    for (int f = 0; f < EFD; f++) m += sa[f] * Tp[f * DDI];
    atomicAdd(&g_h2[t * DDI + o], m);
}

__global__ void __launch_bounds__(DDI) k_AB(const float* __restrict__ Wl1,
                                            const float* __restrict__ bl1,
                                            const float* __restrict__ Wl2,
                                            const float* __restrict__ bl2) {
    __shared__ float sh[DDI];
    int g = blockIdx.x, o = threadIdx.x;
    sh[o] = fmaxf(g_h2[g * DDI + o], 0.f);
    __syncthreads();
    float a = bl1[o], b = bl2[o];
    for (int i = 0; i < DDI; i++) {
        a += sh[i] * Wl1[i * DDI + o];
        b += sh[i] * Wl2[i * DDI + o];
    }
    g_A[g * DDI + o] = a;
    g_B[g * DDI + o] = b;
}

__global__ void __launch_bounds__(DDI) k_edges(const int* __restrict__ dei,
                                               const int* __restrict__ nei,
                                               float* __restrict__ out) {
    int e = blockIdx.x, neg = blockIdx.y, o = threadIdx.x;
    const int* idx = neg ? nei : dei;
    int s = idx[e], t = idx[NEDDI + e];
    float av = g_A[s * DDI + o], bv = g_B[t * DDI + o];
    if (!neg) out[1 + 2 * NEDDI + (size_t)e * DDI + o] = av;
    float d = av * bv;
    __shared__ float sred[4];
    int lane = o & 31, w = o >> 5;
#pragma unroll
    for (int k = 16; k > 0; k >>= 1) d += __shfl_xor_sync(0xFFFFFFFFu, d, k);
    if (lane == 0) sred[w] = d;
    __syncthreads();
    if (o == 0) {
        float tot = sred[0] + sred[1] + sred[2] + sred[3];
        out[1 + neg * NEDDI + e] = tot;
        atomicAdd(&g_lsum[neg], sp_f(neg ? tot : -tot));
    }
}

__global__ void k_final(float* out) {
    out[0] = g_lsum[0] * (1.0f / NEDDI) + g_lsum[1] * (1.0f / NEDDI);
}

extern "C" void kernel_launch(void* const* d_in, const int* in_sizes, int n_in,
                              void* d_out, int out_size) {
    const float* x    = (const float*)d_in[0];
    const float* ew   = (const float*)d_in[1];
    const float* dattr= (const float*)d_in[2];
    const float* W1 = (const float*)d_in[4],  *b1 = (const float*)d_in[5];
    const float* s1r= (const float*)d_in[6],  *s1n= (const float*)d_in[7],  *s1b= (const float*)d_in[8];
    const float* W2 = (const float*)d_in[9],  *b2 = (const float*)d_in[10];
    const float* s2r= (const float*)d_in[11], *s2n= (const float*)d_in[12], *s2b= (const float*)d_in[13];
    const float* W3 = (const float*)d_in[14], *b3 = (const float*)d_in[15];
    const float* s3r= (const float*)d_in[16], *s3n= (const float*)d_in[17], *s3b= (const float*)d_in[18];
    const float* Wnn= (const float*)d_in[19], *bnn= (const float*)d_in[20];
    const float* Wrt= (const float*)d_in[21], *bc4= (const float*)d_in[22];
    const float* Wl1= (const float*)d_in[23], *bl1= (const float*)d_in[24];
    const float* Wl2= (const float*)d_in[25], *bl2= (const float*)d_in[26];
    const int* ei   = (const int*)d_in[27];
    const int* dei  = (const int*)d_in[28];
    const int* nei  = (const int*)d_in[29];
    float* out = (float*)d_out;

    static float* gpool_dev = nullptr;
    if (!gpool_dev) cudaGetSymbolAddress((void**)&gpool_dev, g_pool);

    int smem = (int)sizeof(SG);
    cudaFuncSetAttribute(k_graph<1024, 512>, cudaFuncAttributeMaxDynamicSharedMemorySize, smem);
    cudaFuncSetAttribute(k_graph<512, 256>,  cudaFuncAttributeMaxDynamicSharedMemorySize, smem);
    cudaFuncSetAttribute(k_graph<256, 128>,  cudaFuncAttributeMaxDynamicSharedMemorySize, smem);

    k_init<<<512, 512>>>(ei, ew);
    k_gemm<<<dim3(8, G_), 128>>>(x, W1);
    k_graph<1024, 512><<<G_, NT, smem>>>(s1r, s1n, s1b, b1);
    k_gemm<<<dim3(4, G_), 128>>>(gpool_dev, W2);
    k_graph<512, 256><<<G_, NT, smem>>>(s2r, s2n, s2b, b2);
    k_gemm<<<dim3(2, G_), 128>>>(gpool_dev, W3);
    k_graph<256, 128><<<G_, NT, smem>>>(s3r, s3n, s3b, b3);
    k_T<<<G_, DDI>>>(Wnn, bnn);
    k_hinit<<<G_, DDI>>>(Wrt, bc4);
    k_msg<<<NEDDI, DDI>>>(dattr, dei);
    k_AB<<<G_, DDI>>>(Wl1, bl1, Wl2, bl2);
    k_edges<<<dim3(NEDDI, 2), DDI>>>(dei, nei, out);
    k_final<<<1, 1>>>(out);
}

// round 4
// speedup vs baseline: 1.2365x; 1.2365x over previous
#include <cuda_runtime.h>
#include <cuda_bf16.h>
#include <math.h>

#define G_    256
#define NMAX  1024
#define EMAX  4096
#define CH    64
#define DDI   128
#define EFD   16
#define NEDDI 4096
#define NT    512
#define NWARP 16

typedef unsigned long long ull;

__device__ float g_h   [(size_t)G_ * NMAX * CH];
__device__ float g_gcn [(size_t)G_ * NMAX * CH];
__device__ float g_pool[(size_t)G_ * NMAX * CH];
__device__ short g_es  [(size_t)G_ * EMAX];
__device__ short g_et  [(size_t)G_ * EMAX];
__device__ float g_ew  [(size_t)G_ * EMAX];
__device__ int   g_ecnt[G_];
__device__ float g_feat[G_ * 2 * CH];
__device__ float g_T   [(size_t)G_ * EFD * DDI];
__device__ float g_tb  [G_ * DDI];
__device__ float g_h2  [G_ * DDI];
__device__ float g_A   [G_ * DDI];
__device__ float g_B   [G_ * DDI];
__device__ float g_lsum[2];

__device__ __forceinline__ ull fma2(ull a, ull b, ull c) {
    ull d; asm("fma.rn.f32x2 %0, %1, %2, %3;" : "=l"(d) : "l"(a), "l"(b), "l"(c)); return d;
}
__device__ __forceinline__ ull pk2(float a) {
    ull r; asm("mov.b64 %0, {%1, %2};" : "=l"(r) : "f"(a), "f"(a)); return r;
}
__device__ __forceinline__ unsigned keyflip(float f) {
    unsigned u = __float_as_uint(f);
    return (u & 0x80000000u) ? ~u : (u | 0x80000000u);
}
__device__ __forceinline__ float sp_f(float x) {
    return fmaxf(x, 0.f) + log1pf(expf(-fabsf(x)));
}

__global__ void k_init(const int* __restrict__ ei, const float* __restrict__ ew) {
    size_t stride = (size_t)gridDim.x * blockDim.x;
    size_t t0 = (size_t)blockIdx.x * blockDim.x + threadIdx.x;
    for (size_t i = t0; i < (size_t)G_ * EMAX; i += stride) {
        size_t g = i >> 12, e = i & 4095;
        const int* base = ei + g * 2 * EMAX;
        g_es[i] = (short)base[e];
        g_et[i] = (short)base[EMAX + e];
        g_ew[i] = ew[i];
    }
    for (size_t i = t0; i < (size_t)G_ * 2 * CH; i += stride) g_feat[i] = 0.f;
    if (t0 < G_) g_ecnt[t0] = EMAX;
    if (t0 < 2)  g_lsum[t0] = 0.f;
}

// 256 rows/block, 256 threads: each thread 4 rows x 16 cols (8 packed ull)
__global__ void __launch_bounds__(256) k_gemm(const float* __restrict__ xin,
                                              const float* __restrict__ W) {
    __shared__ __align__(16) float sW[CH * CH];
    __shared__ __align__(16) float sX[16 * 260];
    int tid = threadIdx.x;
    {
        const float4* w4 = (const float4*)W;
        float4* s4 = (float4*)sW;
        for (int i = tid; i < CH * CH / 4; i += 256) s4[i] = w4[i];
    }
    int g = blockIdx.y;
    size_t rowbase = (size_t)g * NMAX + blockIdx.x * 256;
    const float* xbase = xin + rowbase * CH;
    int colgrp = tid & 3, rowgrp = tid >> 2;
    int r0 = rowgrp * 4;
    const ull* sWu = (const ull*)sW;
    ull acc[4][8];
#pragma unroll
    for (int i = 0; i < 4; i++)
#pragma unroll
        for (int o = 0; o < 8; o++) acc[i][o] = 0ull;

#pragma unroll 1
    for (int kc = 0; kc < 4; kc++) {
        __syncthreads();
#pragma unroll
        for (int j = 0; j < 4; j++) {
            int idx = tid + j * 256;
            int row = idx >> 2, kp = idx & 3;
            float4 v = *(const float4*)(xbase + row * CH + kc * 16 + kp * 4);
            int kl = kp * 4;
            sX[(kl + 0) * 260 + row] = v.x;
            sX[(kl + 1) * 260 + row] = v.y;
            sX[(kl + 2) * 260 + row] = v.z;
            sX[(kl + 3) * 260 + row] = v.w;
        }
        __syncthreads();
#pragma unroll
        for (int kl = 0; kl < 16; kl++) {
            int k = kc * 16 + kl;
            float4 xv = *(const float4*)(sX + kl * 260 + r0);
            const ull* wr = sWu + k * 32 + colgrp * 8;
            ull x0 = pk2(xv.x), x1 = pk2(xv.y), x2 = pk2(xv.z), x3 = pk2(xv.w);
#pragma unroll
            for (int o = 0; o < 8; o++) {
                ull wv = wr[o];
                acc[0][o] = fma2(x0, wv, acc[0][o]);
                acc[1][o] = fma2(x1, wv, acc[1][o]);
                acc[2][o] = fma2(x2, wv, acc[2][o]);
                acc[3][o] = fma2(x3, wv, acc[3][o]);
            }
        }
    }
#pragma unroll
    for (int i = 0; i < 4; i++) {
        ull* orow = (ull*)(g_h + (rowbase + r0 + i) * CH) + colgrp * 8;
#pragma unroll
        for (int o = 0; o < 8; o++) orow[o] = acc[i][o];
    }
}

struct SG {
    ull   keys[NMAX];
    short es[EMAX]; short et[EMAX]; float ew[EMAX]; short eord[EMAX];
    int   rowptr[NMAX + 1]; int cnt[NMAX];
    float dinv[NMAX]; float pdot[NMAX]; float score[NMAX];
    short newid[NMAX];
    float wroot[CH], wnbr[CH], bias[CH];
    float pmax[NWARP][CH]; float psum[NWARP][CH];
    int   scan[NWARP + 1];
    float sbv; int base;
};

__device__ int blockScanExcl(int v, int* sscan, int tid, int* totalOut) {
    __syncthreads();
    int lane = tid & 31, w = tid >> 5, x = v;
#pragma unroll
    for (int o = 1; o < 32; o <<= 1) {
        int y = __shfl_up_sync(0xFFFFFFFFu, x, o);
        if (lane >= o) x += y;
    }
    if (lane == 31) sscan[w] = x;
    __syncthreads();
    if (w == 0) {
        int t = (lane < NWARP) ? sscan[lane] : 0;
#pragma unroll
        for (int o = 1; o < NWARP; o <<= 1) {
            int y = __shfl_up_sync(0xFFFFFFFFu, t, o);
            if (lane >= o) t += y;
        }
        if (lane < NWARP) sscan[lane] = t;
    }
    __syncthreads();
    int wOff = w ? sscan[w - 1] : 0;
    *totalOut = sscan[NWARP - 1];
    return wOff + (x - v);
}

__device__ __forceinline__ void shflPhase(ull& e0, ull& e1, int delta, bool dsc, int tid) {
    ull p0 = __shfl_xor_sync(0xFFFFFFFFu, e0, delta);
    ull p1 = __shfl_xor_sync(0xFFFFFFFFu, e1, delta);
    bool lower = ((tid & delta) == 0);
    if (dsc == lower) {
        e0 = (e0 > p0) ? e0 : p0;
        e1 = (e1 > p1) ? e1 : p1;
    } else {
        e0 = (e0 < p0) ? e0 : p0;
        e1 = (e1 < p1) ? e1 : p1;
    }
}

template <int N, int K>
__global__ void __launch_bounds__(NT) k_graph(const float* __restrict__ sroot,
                                              const float* __restrict__ snbr,
                                              const float* __restrict__ sbp,
                                              const float* __restrict__ bvec) {
    extern __shared__ char smraw[];
    SG& S = *reinterpret_cast<SG*>(smraw);
    int tid = threadIdx.x, lane = tid & 31, w = tid >> 5;
    int g = blockIdx.x;
    int E = g_ecnt[g];
    size_t gbase = (size_t)g * NMAX * CH;
    size_t ebase = (size_t)g * EMAX;

    for (int e = tid; e < E; e += NT) {
        S.es[e] = g_es[ebase + e]; S.et[e] = g_et[ebase + e]; S.ew[e] = g_ew[ebase + e];
    }
    for (int i = tid; i < N; i += NT) { S.dinv[i] = 1.0f; S.cnt[i] = 0; }
    if (tid < CH) { S.wroot[tid] = sroot[tid]; S.wnbr[tid] = snbr[tid]; S.bias[tid] = bvec[tid]; }
    if (tid == 0) S.sbv = sbp[0];
    __syncthreads();

    for (int e = tid; e < E; e += NT) {
        int t = S.et[e];
        atomicAdd(&S.dinv[t], S.ew[e]);
        atomicAdd(&S.cnt[t], 1);
    }
    __syncthreads();
    for (int i = tid; i < N; i += NT) S.dinv[i] = rsqrtf(S.dinv[i]);

    const int EPT = (N + NT - 1) / NT;
    int b0 = tid * EPT, mysum = 0;
#pragma unroll
    for (int q = 0; q < EPT; q++) { int i = b0 + q; if (i < N) mysum += S.cnt[i]; }
    int tot;
    int off = blockScanExcl(mysum, S.scan, tid, &tot);
#pragma unroll
    for (int q = 0; q < EPT; q++) {
        int i = b0 + q;
        if (i < N) { S.rowptr[i] = off; off += S.cnt[i]; }
    }
    if (tid == 0) S.rowptr[N] = E;
    __syncthreads();
    for (int i = tid; i < N; i += NT) S.cnt[i] = 0;
    __syncthreads();
    for (int e = tid; e < E; e += NT) {
        int t = S.et[e];
        S.eord[S.rowptr[t] + atomicAdd(&S.cnt[t], 1)] = (short)e;
    }
    __syncthreads();

    const int c0 = lane, c1 = lane + 32;
    for (int t = w; t < N; t += NWARP) {
        const float* hr = g_h + gbase + (size_t)t * CH;
        float dt = S.dinv[t];
        float a0 = dt * dt * hr[c0], a1 = dt * dt * hr[c1];
        int rb = S.rowptr[t], re = S.rowptr[t + 1];
#pragma unroll 2
        for (int ii = rb; ii < re; ii++) {
            int e = S.eord[ii];
            int s = S.es[e];
            float cf = S.dinv[s] * S.ew[e] * dt;
            const float* hs = g_h + gbase + (size_t)s * CH;
            a0 += cf * hs[c0];
            a1 += cf * hs[c1];
        }
        float v0 = fmaxf(a0 + S.bias[c0], 0.f), v1 = fmaxf(a1 + S.bias[c1], 0.f);
        float* gr = g_gcn + gbase + (size_t)t * CH;
        gr[c0] = v0; gr[c1] = v1;
        float pv = v0 * S.wnbr[c0] + v1 * S.wnbr[c1];
        float qv = v0 * S.wroot[c0] + v1 * S.wroot[c1];
#pragma unroll
        for (int o = 16; o > 0; o >>= 1) {
            pv += __shfl_xor_sync(0xFFFFFFFFu, pv, o);
            qv += __shfl_xor_sync(0xFFFFFFFFu, qv, o);
        }
        if (lane == 0) { S.pdot[t] = pv; S.score[t] = qv + S.sbv; }
    }
    __syncthreads();

    for (int t = tid; t < N; t += NT) {
        float acc = 0.f;
        for (int ii = S.rowptr[t]; ii < S.rowptr[t + 1]; ii++) {
            int e = S.eord[ii];
            acc += S.ew[e] * S.pdot[S.es[e]];
        }
        S.score[t] += acc;
    }
    __syncthreads();

    // hybrid bitonic sort: regs+shfl for j<=32, smem for j>=64; descending
    const bool act = (tid < N / 2);
    ull e0 = 0, e1 = 0;
    if (act) {
        int i0 = 2 * tid;
        e0 = ((ull)keyflip(S.score[i0]) << 32) | (ull)(0xFFFFFFFFu - (unsigned)i0);
        e1 = ((ull)keyflip(S.score[i0 + 1]) << 32) | (ull)(0xFFFFFFFFu - (unsigned)(i0 + 1));
        for (int k2 = 2; k2 <= 64; k2 <<= 1) {
            bool dsc = (((2 * tid) & k2) == 0);
            for (int j = k2 >> 1; j >= 2; j >>= 1) shflPhase(e0, e1, j >> 1, dsc, tid);
            if (dsc) { ull mx = (e0 > e1) ? e0 : e1; e1 = (e0 > e1) ? e1 : e0; e0 = mx; }
            else     { ull mn = (e0 < e1) ? e0 : e1; e1 = (e0 < e1) ? e1 : e0; e0 = mn; }
        }
    }
    for (int k2 = 128; k2 <= N; k2 <<= 1) {
        if (act) { S.keys[2 * tid] = e0; S.keys[2 * tid + 1] = e1; }
        __syncthreads();
        for (int j = k2 >> 1; j >= 64; j >>= 1) {
            for (int i = tid; i < N; i += NT) {
                int ij = i ^ j;
                if (ij > i) {
                    ull a = S.keys[i], b = S.keys[ij];
                    bool dsc = ((i & k2) == 0);
                    if (dsc ? (a < b) : (a > b)) { S.keys[i] = b; S.keys[ij] = a; }
                }
            }
            __syncthreads();
        }
        if (act) {
            e0 = S.keys[2 * tid]; e1 = S.keys[2 * tid + 1];
            bool dsc = (((2 * tid) & k2) == 0);
            for (int j = 32; j >= 2; j >>= 1) shflPhase(e0, e1, j >> 1, dsc, tid);
            if (dsc) { ull mx = (e0 > e1) ? e0 : e1; e1 = (e0 > e1) ? e1 : e0; e0 = mx; }
            else     { ull mn = (e0 < e1) ? e0 : e1; e1 = (e0 < e1) ? e1 : e0; e0 = mn; }
        }
        __syncthreads();
    }
    if (act) { S.keys[2 * tid] = e0; S.keys[2 * tid + 1] = e1; }
    __syncthreads();

    S.pmax[w][c0] = -3.4e38f; S.pmax[w][c1] = -3.4e38f;
    S.psum[w][c0] = 0.f;      S.psum[w][c1] = 0.f;
    for (int j = w; j < K; j += NWARP) {
        unsigned idx = 0xFFFFFFFFu - (unsigned)(S.keys[j] & 0xFFFFFFFFull);
        float tv = tanhf(S.score[idx]);
        const float* gr = g_gcn + gbase + (size_t)idx * CH;
        float u0 = gr[c0] * tv, u1 = gr[c1] * tv;
        float* pr = g_pool + gbase + (size_t)j * CH;
        pr[c0] = u0; pr[c1] = u1;
        S.pmax[w][c0] = fmaxf(S.pmax[w][c0], u0);
        S.pmax[w][c1] = fmaxf(S.pmax[w][c1], u1);
        S.psum[w][c0] += u0; S.psum[w][c1] += u1;
    }
    __syncthreads();
    if (tid < CH) {
        float mx = -3.4e38f, sm = 0.f;
#pragma unroll
        for (int ww = 0; ww < NWARP; ww++) {
            mx = fmaxf(mx, S.pmax[ww][tid]);
            sm += S.psum[ww][tid];
        }
        g_feat[g * 2 * CH + tid]      += mx;
        g_feat[g * 2 * CH + CH + tid] += sm * (1.0f / K);
    }

    // remap + unordered ballot compaction straight to global
    for (int i = tid; i < N; i += NT) S.newid[i] = -1;
    __syncthreads();
    for (int j = tid; j < K; j += NT) {
        unsigned idx = 0xFFFFFFFFu - (unsigned)(S.keys[j] & 0xFFFFFFFFull);
        S.newid[idx] = (short)j;
    }
    if (tid == 0) S.base = 0;
    __syncthreads();
    int iters = (E + NT - 1) / NT;
    for (int c = 0; c < iters; c++) {
        int e = c * NT + tid;
        short sv = 0, tv2 = 0; float wv = 0.f; bool keep = false;
        if (e < E) {
            sv = S.newid[S.es[e]]; tv2 = S.newid[S.et[e]]; wv = S.ew[e];
            keep = (sv >= 0) && (tv2 >= 0);
        }
        unsigned m = __ballot_sync(0xFFFFFFFFu, keep);
        int cnt = __popc(m);
        int pos = 0;
        if (lane == 0 && cnt) pos = atomicAdd(&S.base, cnt);
        pos = __shfl_sync(0xFFFFFFFFu, pos, 0) + __popc(m & ((1u << lane) - 1u));
        if (keep) {
            g_es[ebase + pos] = sv; g_et[ebase + pos] = tv2; g_ew[ebase + pos] = wv;
        }
    }
    __syncthreads();
    if (tid == 0) g_ecnt[g] = S.base;
}

// T/tb/h2 as one GEMM: out[256,18*128] = feat[256,128] @ B
__global__ void __launch_bounds__(256) k_prep(const float* __restrict__ Wnn,
                                              const float* __restrict__ bnn,
                                              const float* __restrict__ Wroot,
                                              const float* __restrict__ bc4) {
    __shared__ __align__(16) float sF[16 * 132];
    int tid = threadIdx.x;
    int f = blockIdx.x, rb = blockIdx.y;
    const float* B = (f < 16) ? (Wnn + (size_t)f * 16384) : (f == 16 ? bnn : Wroot);
    int colgrp = tid & 7, rowgrp = tid >> 3;
    int c0 = colgrp * 16, r0 = rowgrp * 4;
    const float* fbase = g_feat + (size_t)(rb * 128) * 128;
    ull acc[4][8];
#pragma unroll
    for (int i = 0; i < 4; i++)
#pragma unroll
        for (int o = 0; o < 8; o++) acc[i][o] = 0ull;

#pragma unroll 1
    for (int kc = 0; kc < 8; kc++) {
        __syncthreads();
#pragma unroll
        for (int j = 0; j < 2; j++) {
            int idx = tid + j * 256;
            int row = idx >> 2, kp = idx & 3;
            float4 v = *(const float4*)(fbase + row * 128 + kc * 16 + kp * 4);
            int kl = kp * 4;
            sF[(kl + 0) * 132 + row] = v.x;
            sF[(kl + 1) * 132 + row] = v.y;
            sF[(kl + 2) * 132 + row] = v.z;
            sF[(kl + 3) * 132 + row] = v.w;
        }
        __syncthreads();
#pragma unroll
        for (int kl = 0; kl < 16; kl++) {
            int k = kc * 16 + kl;
            float4 xv = *(const float4*)(sF + kl * 132 + r0);
            const ull* wr = (const ull*)(B + k * 128 + c0);
            ull x0 = pk2(xv.x), x1 = pk2(xv.y), x2 = pk2(xv.z), x3 = pk2(xv.w);
#pragma unroll
            for (int o = 0; o < 8; o++) {
                ull wv = wr[o];
                acc[0][o] = fma2(x0, wv, acc[0][o]);
                acc[1][o] = fma2(x1, wv, acc[1][o]);
                acc[2][o] = fma2(x2, wv, acc[2][o]);
                acc[3][o] = fma2(x3, wv, acc[3][o]);
            }
        }
    }
#pragma unroll
    for (int i = 0; i < 4; i++) {
        int g = rb * 128 + r0 + i;
        if (f < 16) {
            ull* op = (ull*)(g_T + ((size_t)g * EFD + f) * DDI + c0);
#pragma unroll
            for (int o = 0; o < 8; o++) op[o] = acc[i][o];
        } else if (f == 16) {
            ull* op = (ull*)(g_tb + g * DDI + c0);
#pragma unroll
            for (int o = 0; o < 8; o++) op[o] = acc[i][o];
        } else {
            float2* op = (float2*)(g_h2 + g * DDI + c0);
#pragma unroll
            for (int o = 0; o < 8; o++) {
                float2 a = *(float2*)&acc[i][o];
                a.x += bc4[c0 + 2 * o];
                a.y += bc4[c0 + 2 * o + 1];
                op[o] = a;
            }
        }
    }
}

__global__ void __launch_bounds__(DDI) k_msg(const float* __restrict__ attr,
                                             const int* __restrict__ dei) {
    int e = blockIdx.x, o = threadIdx.x;
    int s = dei[e], t = dei[NEDDI + e];
    __shared__ float sa[EFD];
    if (o < EFD) sa[o] = attr[e * EFD + o];
    __syncthreads();
    const float* Tp = g_T + (size_t)s * EFD * DDI + o;
    float m = g_tb[s * DDI + o];
#pragma unroll
    for (int f = 0; f < EFD; f++) m += sa[f] * Tp[f * DDI];
    atomicAdd(&g_h2[t * DDI + o], m);
}

__global__ void __launch_bounds__(DDI) k_AB(const float* __restrict__ Wl1,
                                            const float* __restrict__ bl1,
                                            const float* __restrict__ Wl2,
                                            const float* __restrict__ bl2) {
    __shared__ float sh[DDI];
    int g = blockIdx.x, o = threadIdx.x;
    sh[o] = fmaxf(g_h2[g * DDI + o], 0.f);
    __syncthreads();
    float a = bl1[o], b = bl2[o];
    for (int i = 0; i < DDI; i++) {
        a += sh[i] * Wl1[i * DDI + o];
        b += sh[i] * Wl2[i * DDI + o];
    }
    g_A[g * DDI + o] = a;
    g_B[g * DDI + o] = b;
}

__global__ void __launch_bounds__(DDI) k_edges(const int* __restrict__ dei,
                                               const int* __restrict__ nei,
                                               float* __restrict__ out) {
    int e = blockIdx.x, neg = blockIdx.y, o = threadIdx.x;
    const int* idx = neg ? nei : dei;
    int s = idx[e], t = idx[NEDDI + e];
    float av = g_A[s * DDI + o], bv = g_B[t * DDI + o];
    if (!neg) out[1 + 2 * NEDDI + (size_t)e * DDI + o] = av;
    float d = av * bv;
    __shared__ float sred[4];
    int lane = o & 31, w = o >> 5;
#pragma unroll
    for (int k = 16; k > 0; k >>= 1) d += __shfl_xor_sync(0xFFFFFFFFu, d, k);
    if (lane == 0) sred[w] = d;
    __syncthreads();
    if (o == 0) {
        float tot = sred[0] + sred[1] + sred[2] + sred[3];
        out[1 + neg * NEDDI + e] = tot;
        atomicAdd(&g_lsum[neg], sp_f(neg ? tot : -tot));
    }
}

__global__ void k_final(float* out) {
    out[0] = g_lsum[0] * (1.0f / NEDDI) + g_lsum[1] * (1.0f / NEDDI);
}

extern "C" void kernel_launch(void* const* d_in, const int* in_sizes, int n_in,
                              void* d_out, int out_size) {
    const float* x    = (const float*)d_in[0];
    const float* ew   = (const float*)d_in[1];
    const float* dattr= (const float*)d_in[2];
    const float* W1 = (const float*)d_in[4],  *b1 = (const float*)d_in[5];
    const float* s1r= (const float*)d_in[6],  *s1n= (const float*)d_in[7],  *s1b= (const float*)d_in[8];
    const float* W2 = (const float*)d_in[9],  *b2 = (const float*)d_in[10];
    const float* s2r= (const float*)d_in[11], *s2n= (const float*)d_in[12], *s2b= (const float*)d_in[13];
    const float* W3 = (const float*)d_in[14], *b3 = (const float*)d_in[15];
    const float* s3r= (const float*)d_in[16], *s3n= (const float*)d_in[17], *s3b= (const float*)d_in[18];
    const float* Wnn= (const float*)d_in[19], *bnn= (const float*)d_in[20];
    const float* Wrt= (const float*)d_in[21], *bc4= (const float*)d_in[22];
    const float* Wl1= (const float*)d_in[23], *bl1= (const float*)d_in[24];
    const float* Wl2= (const float*)d_in[25], *bl2= (const float*)d_in[26];
    const int* ei   = (const int*)d_in[27];
    const int* dei  = (const int*)d_in[28];
    const int* nei  = (const int*)d_in[29];
    float* out = (float*)d_out;

    static float* gpool_dev = nullptr;
    if (!gpool_dev) cudaGetSymbolAddress((void**)&gpool_dev, g_pool);

    int smem = (int)sizeof(SG);
    cudaFuncSetAttribute(k_graph<1024, 512>, cudaFuncAttributeMaxDynamicSharedMemorySize, smem);
    cudaFuncSetAttribute(k_graph<512, 256>,  cudaFuncAttributeMaxDynamicSharedMemorySize, smem);
    cudaFuncSetAttribute(k_graph<256, 128>,  cudaFuncAttributeMaxDynamicSharedMemorySize, smem);

    k_init<<<512, 512>>>(ei, ew);
    k_gemm<<<dim3(4, G_), 256>>>(x, W1);
    k_graph<1024, 512><<<G_, NT, smem>>>(s1r, s1n, s1b, b1);
    k_gemm<<<dim3(2, G_), 256>>>(gpool_dev, W2);
    k_graph<512, 256><<<G_, NT, smem>>>(s2r, s2n, s2b, b2);
    k_gemm<<<dim3(1, G_), 256>>>(gpool_dev, W3);
    k_graph<256, 128><<<G_, NT, smem>>>(s3r, s3n, s3b, b3);
    k_prep<<<dim3(18, 2), 256>>>(Wnn, bnn, Wrt, bc4);
    k_msg<<<NEDDI, DDI>>>(dattr, dei);
    k_AB<<<G_, DDI>>>(Wl1, bl1, Wl2, bl2);
    k_edges<<<dim3(NEDDI, 2), DDI>>>(dei, nei, out);
    k_final<<<1, 1>>>(out);
}